// round 1
// baseline (speedup 1.0000x reference)
#include <cuda_runtime.h>

#define Bsz 8
#define Cch 512
#define HWs 1024
#define NH 8
#define DH 64
#define NGROUPS 32
#define CPG 16
#define EPSV 1e-5f

// Scratch (device globals: allocation-free per harness rules)
__device__ float g_xn[(size_t)Bsz * Cch * HWs];        // 16 MB  normalized input
__device__ float g_qkv[(size_t)Bsz * 3 * Cch * HWs];   // 48 MB  qkv activations
__device__ float g_att[(size_t)Bsz * Cch * HWs];       // 16 MB  attention output

// ---------------------------------------------------------------------------
// GroupNorm: one block per (batch, group); 16 ch x 1024 px contiguous chunk
// ---------------------------------------------------------------------------
__global__ __launch_bounds__(256) void gn_kernel(const float* __restrict__ x,
                                                 const float* __restrict__ gamma,
                                                 const float* __restrict__ beta) {
    int b = blockIdx.x >> 5, g = blockIdx.x & 31;
    size_t base = ((size_t)b * Cch + g * CPG) * HWs;
    const float4* xin = (const float4*)(x + base);
    float4* xo = (float4*)(g_xn + base);
    int tid = threadIdx.x;
    const int N4 = CPG * HWs / 4;  // 4096 float4s
    float s = 0.f, ss = 0.f;
    for (int i = tid; i < N4; i += 256) {
        float4 v = xin[i];
        s += v.x + v.y + v.z + v.w;
        ss += v.x * v.x + v.y * v.y + v.z * v.z + v.w * v.w;
    }
    __shared__ float red[64];
    #pragma unroll
    for (int o = 16; o; o >>= 1) {
        s += __shfl_xor_sync(~0u, s, o);
        ss += __shfl_xor_sync(~0u, ss, o);
    }
    if ((tid & 31) == 0) { red[tid >> 5] = s; red[32 + (tid >> 5)] = ss; }
    __syncthreads();
    if (tid < 32) {
        s = (tid < 8) ? red[tid] : 0.f;
        ss = (tid < 8) ? red[32 + tid] : 0.f;
        #pragma unroll
        for (int o = 4; o; o >>= 1) {
            s += __shfl_xor_sync(~0u, s, o);
            ss += __shfl_xor_sync(~0u, ss, o);
        }
        if (tid == 0) { red[0] = s; red[1] = ss; }
    }
    __syncthreads();
    const float invN = 1.f / (CPG * HWs);
    float mean = red[0] * invN;
    float var = red[1] * invN - mean * mean;
    float inv = rsqrtf(var + EPSV);
    for (int i = tid; i < N4; i += 256) {
        int c = g * CPG + (i >> 8);  // 256 float4s per channel
        float ga = gamma[c] * inv;
        float be = beta[c] - mean * ga;
        float4 v = xin[i];
        v.x = v.x * ga + be;
        v.y = v.y * ga + be;
        v.z = v.z * ga + be;
        v.w = v.w * ga + be;
        xo[i] = v;
    }
}

// ---------------------------------------------------------------------------
// SGEMM: Y[z][m][n] = sum_k W[m][k] * X[z][k][n]  (+ R[z][m][n])
// 128x128 block tile, BK=8, 256 threads, 8x8 microtile
// ---------------------------------------------------------------------------
template <int MD, int KD, bool ADD>
__global__ __launch_bounds__(256) void gemm_kernel(const float* __restrict__ W,
                                                   const float* __restrict__ X,
                                                   float* __restrict__ Y,
                                                   const float* __restrict__ R) {
    __shared__ float As[8][128];  // A transposed: As[k][m]
    __shared__ float Bs[8][128];
    int tid = threadIdx.x;
    int tx = tid & 15, ty = tid >> 4;
    int bn = blockIdx.x * 128, bm = blockIdx.y * 128;
    const float* Xb = X + (size_t)blockIdx.z * KD * HWs;

    float acc[8][8];
    #pragma unroll
    for (int i = 0; i < 8; i++)
        #pragma unroll
        for (int j = 0; j < 8; j++) acc[i][j] = 0.f;

    int aRow = tid >> 1, aCol = (tid & 1) * 4;
    int bRow = tid >> 5, bCol = (tid & 31) * 4;
    const float* Aptr = W + (size_t)(bm + aRow) * KD + aCol;
    const float* Bptr = Xb + (size_t)bRow * HWs + bn + bCol;

    for (int k0 = 0; k0 < KD; k0 += 8) {
        float4 av = *(const float4*)(Aptr + k0);
        float4 bv = *(const float4*)(Bptr + (size_t)k0 * HWs);
        __syncthreads();
        As[aCol + 0][aRow] = av.x;
        As[aCol + 1][aRow] = av.y;
        As[aCol + 2][aRow] = av.z;
        As[aCol + 3][aRow] = av.w;
        *(float4*)&Bs[bRow][bCol] = bv;
        __syncthreads();
        #pragma unroll
        for (int k = 0; k < 8; k++) {
            float a[8], bb[8];
            *(float4*)&a[0] = *(const float4*)&As[k][ty * 8];
            *(float4*)&a[4] = *(const float4*)&As[k][ty * 8 + 4];
            *(float4*)&bb[0] = *(const float4*)&Bs[k][tx * 8];
            *(float4*)&bb[4] = *(const float4*)&Bs[k][tx * 8 + 4];
            #pragma unroll
            for (int i = 0; i < 8; i++)
                #pragma unroll
                for (int j = 0; j < 8; j++) acc[i][j] = fmaf(a[i], bb[j], acc[i][j]);
        }
    }

    size_t ybase = (size_t)blockIdx.z * MD * HWs;
    #pragma unroll
    for (int i = 0; i < 8; i++) {
        size_t off = ybase + (size_t)(bm + ty * 8 + i) * HWs + bn + tx * 8;
        float4 v0 = *(float4*)&acc[i][0];
        float4 v1 = *(float4*)&acc[i][4];
        if (ADD) {
            float4 r0 = *(const float4*)(R + off);
            float4 r1 = *(const float4*)(R + off + 4);
            v0.x += r0.x; v0.y += r0.y; v0.z += r0.z; v0.w += r0.w;
            v1.x += r1.x; v1.y += r1.y; v1.z += r1.z; v1.w += r1.w;
        }
        *(float4*)(Y + off) = v0;
        *(float4*)(Y + off + 4) = v1;
    }
}

// ---------------------------------------------------------------------------
// Flash-style attention: block = (row-tile of 64, head, batch); seq 1024, d 64
// qkv layout: g_qkv[b][o][s], o: q=[0,512), k=[512,1024), v=[1024,1536)
// ---------------------------------------------------------------------------
#define ST 65  // smem tile stride (pad to dodge conflicts)

__global__ __launch_bounds__(256) void attn_kernel() {
    extern __shared__ float sm[];
    float* Qs = sm;             // [64][ST]  Qs[d][i]
    float* Ks = sm + 64 * ST;   // [64][ST]  Ks[d][j]
    float* Vs = sm + 2 * 64 * ST;  // [64][ST]  Vs[j][d]
    float* Ps = sm + 3 * 64 * ST;  // [64][ST]  Ps[j][i]

    int rt = blockIdx.x, h = blockIdx.y, b = blockIdx.z;
    int s0 = rt * 64;
    const float* qkvb = g_qkv + (size_t)b * 3 * Cch * HWs;
    const float* Qg = qkvb + (size_t)(h * DH) * HWs;
    const float* Kg = qkvb + (size_t)(Cch + h * DH) * HWs;
    const float* Vg = qkvb + (size_t)(2 * Cch + h * DH) * HWs;

    int tid = threadIdx.x;
    int tx = tid & 15, ty = tid >> 4;

    for (int idx = tid; idx < 4096; idx += 256) {
        int d = idx >> 6, i = idx & 63;
        Qs[d * ST + i] = Qg[(size_t)d * HWs + s0 + i];
    }

    float m[4], l[4], o[4][4];
    #pragma unroll
    for (int i = 0; i < 4; i++) {
        m[i] = -1e30f;
        l[i] = 0.f;
        #pragma unroll
        for (int j = 0; j < 4; j++) o[i][j] = 0.f;
    }
    const float scale = 0.125f;  // 64^-0.5

    for (int kt = 0; kt < 16; kt++) {
        __syncthreads();
        for (int idx = tid; idx < 4096; idx += 256) {
            int d = idx >> 6, j = idx & 63;
            float kvv = Kg[(size_t)d * HWs + kt * 64 + j];
            float vvv = Vg[(size_t)d * HWs + kt * 64 + j];
            Ks[d * ST + j] = kvv;
            Vs[j * ST + d] = vvv;
        }
        __syncthreads();

        float s[4][4];
        #pragma unroll
        for (int i = 0; i < 4; i++)
            #pragma unroll
            for (int j = 0; j < 4; j++) s[i][j] = 0.f;

        #pragma unroll 4
        for (int d = 0; d < 64; d++) {
            float qv[4], kv[4];
            #pragma unroll
            for (int ii = 0; ii < 4; ii++) qv[ii] = Qs[d * ST + 4 * ty + ii];
            #pragma unroll
            for (int jj = 0; jj < 4; jj++) kv[jj] = Ks[d * ST + 4 * tx + jj];
            #pragma unroll
            for (int ii = 0; ii < 4; ii++)
                #pragma unroll
                for (int jj = 0; jj < 4; jj++) s[ii][jj] = fmaf(qv[ii], kv[jj], s[ii][jj]);
        }

        #pragma unroll
        for (int ii = 0; ii < 4; ii++) {
            #pragma unroll
            for (int jj = 0; jj < 4; jj++) s[ii][jj] *= scale;
            float mx = fmaxf(fmaxf(s[ii][0], s[ii][1]), fmaxf(s[ii][2], s[ii][3]));
            #pragma unroll
            for (int off = 8; off; off >>= 1) mx = fmaxf(mx, __shfl_xor_sync(~0u, mx, off));
            float mnew = fmaxf(m[ii], mx);
            float alpha = __expf(m[ii] - mnew);
            float rsum = 0.f;
            #pragma unroll
            for (int jj = 0; jj < 4; jj++) {
                float p = __expf(s[ii][jj] - mnew);
                s[ii][jj] = p;
                rsum += p;
            }
            #pragma unroll
            for (int off = 8; off; off >>= 1) rsum += __shfl_xor_sync(~0u, rsum, off);
            l[ii] = l[ii] * alpha + rsum;
            m[ii] = mnew;
            #pragma unroll
            for (int dd = 0; dd < 4; dd++) o[ii][dd] *= alpha;
        }

        // stash P transposed: Ps[j][i]
        #pragma unroll
        for (int ii = 0; ii < 4; ii++)
            #pragma unroll
            for (int jj = 0; jj < 4; jj++)
                Ps[(4 * tx + jj) * ST + 4 * ty + ii] = s[ii][jj];
        __syncthreads();

        #pragma unroll 4
        for (int j = 0; j < 64; j++) {
            float pv[4], vv[4];
            #pragma unroll
            for (int ii = 0; ii < 4; ii++) pv[ii] = Ps[j * ST + 4 * ty + ii];
            #pragma unroll
            for (int dd = 0; dd < 4; dd++) vv[dd] = Vs[j * ST + 4 * tx + dd];
            #pragma unroll
            for (int ii = 0; ii < 4; ii++)
                #pragma unroll
                for (int dd = 0; dd < 4; dd++) o[ii][dd] = fmaf(pv[ii], vv[dd], o[ii][dd]);
        }
    }

    __syncthreads();
    // stage O transposed into Qs as [d][i], then coalesced store
    #pragma unroll
    for (int ii = 0; ii < 4; ii++) {
        float invl = 1.f / l[ii];
        #pragma unroll
        for (int dd = 0; dd < 4; dd++)
            Qs[(4 * tx + dd) * ST + 4 * ty + ii] = o[ii][dd] * invl;
    }
    __syncthreads();
    float* Og = g_att + ((size_t)b * Cch + h * DH) * HWs + s0;
    for (int idx = tid; idx < 4096; idx += 256) {
        int d = idx >> 6, i = idx & 63;
        Og[(size_t)d * HWs + i] = Qs[d * ST + i];
    }
}

// ---------------------------------------------------------------------------
extern "C" void kernel_launch(void* const* d_in, const int* in_sizes, int n_in,
                              void* d_out, int out_size) {
    const float* x = (const float*)d_in[0];
    const float* gamma = (const float*)d_in[1];
    const float* beta = (const float*)d_in[2];
    const float* w_qkv = (const float*)d_in[3];
    const float* w_out = (const float*)d_in[4];
    float* out = (float*)d_out;

    void *pxn, *pqkv, *patt;
    cudaGetSymbolAddress(&pxn, g_xn);
    cudaGetSymbolAddress(&pqkv, g_qkv);
    cudaGetSymbolAddress(&patt, g_att);

    gn_kernel<<<Bsz * NGROUPS, 256>>>(x, gamma, beta);

    gemm_kernel<3 * Cch, Cch, false><<<dim3(HWs / 128, 3 * Cch / 128, Bsz), 256>>>(
        w_qkv, (const float*)pxn, (float*)pqkv, nullptr);

    int smem = 4 * 64 * ST * sizeof(float);  // 66560 B
    cudaFuncSetAttribute(attn_kernel, cudaFuncAttributeMaxDynamicSharedMemorySize, smem);
    attn_kernel<<<dim3(16, NH, Bsz), 256, smem>>>();

    gemm_kernel<Cch, Cch, true><<<dim3(HWs / 128, Cch / 128, Bsz), 256>>>(
        w_out, (const float*)patt, out, x);
}

// round 3
// speedup vs baseline: 1.3194x; 1.3194x over previous
#include <cuda_runtime.h>
#include <cuda_bf16.h>
#include <cstdint>

#define Bsz 8
#define Cch 512
#define HWs 1024
#define NH 8
#define DH 64
#define CPG 16
#define EPSV 1e-5f
#define KD 512

// Scratch (device globals: allocation-free per harness rules)
__device__ float g_qkv[(size_t)Bsz * 3 * Cch * HWs];           // 48 MB qkv fp32
__device__ __nv_bfloat16 g_xnT_hi[(size_t)Bsz * HWs * Cch];    // 8 MB  xn^T hi
__device__ __nv_bfloat16 g_xnT_lo[(size_t)Bsz * HWs * Cch];    // 8 MB  xn^T lo
__device__ __nv_bfloat16 g_attT_hi[(size_t)Bsz * HWs * Cch];   // 8 MB  att^T hi
__device__ __nv_bfloat16 g_attT_lo[(size_t)Bsz * HWs * Cch];   // 8 MB  att^T lo
__device__ __nv_bfloat16 g_wq_hi[3 * Cch * KD];
__device__ __nv_bfloat16 g_wq_lo[3 * Cch * KD];
__device__ __nv_bfloat16 g_wo_hi[Cch * KD];
__device__ __nv_bfloat16 g_wo_lo[Cch * KD];

__device__ __forceinline__ void bsplit(float v, __nv_bfloat16& h, __nv_bfloat16& l) {
    h = __float2bfloat16(v);
    l = __float2bfloat16(v - __bfloat162float(h));
}

__device__ __forceinline__ void mma16816(float* c, const uint32_t* a, uint32_t b0, uint32_t b1) {
    asm volatile(
        "mma.sync.aligned.m16n8k16.row.col.f32.bf16.bf16.f32 "
        "{%0,%1,%2,%3}, {%4,%5,%6,%7}, {%8,%9}, {%0,%1,%2,%3};"
        : "+f"(c[0]), "+f"(c[1]), "+f"(c[2]), "+f"(c[3])
        : "r"(a[0]), "r"(a[1]), "r"(a[2]), "r"(a[3]), "r"(b0), "r"(b1));
}

// ---------------------------------------------------------------------------
// GroupNorm -> transposed split-bf16 output  xnT[b][n][c]
// ---------------------------------------------------------------------------
__global__ __launch_bounds__(256) void gn_kernel(const float* __restrict__ x,
                                                 const float* __restrict__ gamma,
                                                 const float* __restrict__ beta) {
    int b = blockIdx.x >> 5, g = blockIdx.x & 31;
    size_t base = ((size_t)b * Cch + g * CPG) * HWs;
    const float4* xin = (const float4*)(x + base);
    int tid = threadIdx.x;
    const int N4 = CPG * HWs / 4;
    float s = 0.f, ss = 0.f;
    for (int i = tid; i < N4; i += 256) {
        float4 v = xin[i];
        s += v.x + v.y + v.z + v.w;
        ss += v.x * v.x + v.y * v.y + v.z * v.z + v.w * v.w;
    }
    __shared__ float red[64];
    __shared__ float sga[CPG], sbe[CPG];
    #pragma unroll
    for (int o = 16; o; o >>= 1) {
        s += __shfl_xor_sync(~0u, s, o);
        ss += __shfl_xor_sync(~0u, ss, o);
    }
    if ((tid & 31) == 0) { red[tid >> 5] = s; red[32 + (tid >> 5)] = ss; }
    __syncthreads();
    if (tid < 32) {
        s = (tid < 8) ? red[tid] : 0.f;
        ss = (tid < 8) ? red[32 + tid] : 0.f;
        #pragma unroll
        for (int o = 4; o; o >>= 1) {
            s += __shfl_xor_sync(~0u, s, o);
            ss += __shfl_xor_sync(~0u, ss, o);
        }
        if (tid == 0) { red[0] = s; red[1] = ss; }
    }
    __syncthreads();
    const float invN = 1.f / (CPG * HWs);
    float mean = red[0] * invN;
    float var = red[1] * invN - mean * mean;
    float inv = rsqrtf(var + EPSV);
    if (tid < CPG) {
        int c = g * CPG + tid;
        float ga = gamma[c] * inv;
        sga[tid] = ga;
        sbe[tid] = beta[c] - mean * ga;
    }
    __syncthreads();
    // pass 2: normalize, split, write transposed
    for (int p = tid; p < HWs; p += 256) {
        __nv_bfloat16 hv[CPG], lv[CPG];
        #pragma unroll
        for (int j = 0; j < CPG; j++) {
            float v = x[base + (size_t)j * HWs + p] * sga[j] + sbe[j];
            bsplit(v, hv[j], lv[j]);
        }
        size_t o = ((size_t)b * HWs + p) * Cch + g * CPG;
        *(uint4*)(g_xnT_hi + o) = *(uint4*)&hv[0];
        *(uint4*)(g_xnT_hi + o + 8) = *(uint4*)&hv[8];
        *(uint4*)(g_xnT_lo + o) = *(uint4*)&lv[0];
        *(uint4*)(g_xnT_lo + o + 8) = *(uint4*)&lv[8];
    }
}

// ---------------------------------------------------------------------------
// weight split
// ---------------------------------------------------------------------------
__global__ __launch_bounds__(256) void split_kernel(const float* __restrict__ src,
                                                    __nv_bfloat16* __restrict__ hi,
                                                    __nv_bfloat16* __restrict__ lo, int n4) {
    int i = blockIdx.x * 256 + threadIdx.x;
    if (i < n4) {
        float4 v = ((const float4*)src)[i];
        __nv_bfloat16 h[4], l[4];
        bsplit(v.x, h[0], l[0]);
        bsplit(v.y, h[1], l[1]);
        bsplit(v.z, h[2], l[2]);
        bsplit(v.w, h[3], l[3]);
        *(uint2*)(hi + 4 * i) = *(uint2*)h;
        *(uint2*)(lo + 4 * i) = *(uint2*)l;
    }
}

// ---------------------------------------------------------------------------
// mma.sync bf16x3 GEMM: Y[z][m][n] = sum_k A[m][k] * B[z][n][k]  (+R)
// Block 128x128, BK=64, 256 threads (8 warps: 4m x 2n), warp tile 32x64.
// smem stride 72 bf16 (conflict-free).
// ---------------------------------------------------------------------------
#define SSTR 72
#define TILE_BYTES (128 * SSTR * 2)        // 18432
#define GEMM_SMEM (4 * TILE_BYTES)         // 73728

template <int MD, bool ADD>
__global__ __launch_bounds__(256) void gemm_mma(const __nv_bfloat16* __restrict__ Ah,
                                                const __nv_bfloat16* __restrict__ Al,
                                                const __nv_bfloat16* __restrict__ Bh,
                                                const __nv_bfloat16* __restrict__ Bl,
                                                float* __restrict__ Y,
                                                const float* __restrict__ R) {
    extern __shared__ char sm[];
    __nv_bfloat16* sAh = (__nv_bfloat16*)sm;
    __nv_bfloat16* sAl = (__nv_bfloat16*)(sm + TILE_BYTES);
    __nv_bfloat16* sBh = (__nv_bfloat16*)(sm + 2 * TILE_BYTES);
    __nv_bfloat16* sBl = (__nv_bfloat16*)(sm + 3 * TILE_BYTES);

    int tid = threadIdx.x, wid = tid >> 5, lane = tid & 31;
    int wm = wid & 3, wn = wid >> 2;
    int g = lane >> 2, t4 = lane & 3;
    int bn = blockIdx.x * 128, bm = blockIdx.y * 128, z = blockIdx.z;

    float acc[2][8][4];
    #pragma unroll
    for (int mt = 0; mt < 2; mt++)
        #pragma unroll
        for (int nt = 0; nt < 8; nt++)
            #pragma unroll
            for (int r = 0; r < 4; r++) acc[mt][nt][r] = 0.f;

    const int frow = tid >> 3, fu = tid & 7;  // fill: row 0..127 (x2), 8-elem chunk
    const __nv_bfloat16* Ahp = Ah + (size_t)(bm + frow) * KD + fu * 8;
    const __nv_bfloat16* Alp = Al + (size_t)(bm + frow) * KD + fu * 8;
    const __nv_bfloat16* Bhp = Bh + ((size_t)z * HWs + bn + frow) * KD + fu * 8;
    const __nv_bfloat16* Blp = Bl + ((size_t)z * HWs + bn + frow) * KD + fu * 8;

    for (int k0 = 0; k0 < KD; k0 += 64) {
        __syncthreads();
        #pragma unroll
        for (int i = 0; i < 4; i++) {
            int row = frow + 32 * i;
            uint32_t doff = row * SSTR + fu * 8;
            *(uint4*)(sAh + doff) = *(const uint4*)(Ahp + (size_t)(32 * i) * KD + k0);
            *(uint4*)(sAl + doff) = *(const uint4*)(Alp + (size_t)(32 * i) * KD + k0);
            *(uint4*)(sBh + doff) = *(const uint4*)(Bhp + (size_t)(32 * i) * KD + k0);
            *(uint4*)(sBl + doff) = *(const uint4*)(Blp + (size_t)(32 * i) * KD + k0);
        }
        __syncthreads();

        #pragma unroll
        for (int kk = 0; kk < 4; kk++) {
            int kb = kk * 16;
            uint32_t ah[2][4], al[2][4];
            #pragma unroll
            for (int mt = 0; mt < 2; mt++) {
                int r0 = wm * 32 + mt * 16 + g;
                uint32_t o00 = r0 * SSTR + kb + t4 * 2;
                uint32_t o10 = (r0 + 8) * SSTR + kb + t4 * 2;
                ah[mt][0] = *(uint32_t*)(sAh + o00);
                ah[mt][1] = *(uint32_t*)(sAh + o10);
                ah[mt][2] = *(uint32_t*)(sAh + o00 + 8);
                ah[mt][3] = *(uint32_t*)(sAh + o10 + 8);
                al[mt][0] = *(uint32_t*)(sAl + o00);
                al[mt][1] = *(uint32_t*)(sAl + o10);
                al[mt][2] = *(uint32_t*)(sAl + o00 + 8);
                al[mt][3] = *(uint32_t*)(sAl + o10 + 8);
            }
            #pragma unroll
            for (int nt = 0; nt < 8; nt++) {
                int nrow = wn * 64 + nt * 8 + g;
                uint32_t ob = nrow * SSTR + kb + t4 * 2;
                uint32_t bh0 = *(uint32_t*)(sBh + ob);
                uint32_t bh1 = *(uint32_t*)(sBh + ob + 8);
                uint32_t bl0 = *(uint32_t*)(sBl + ob);
                uint32_t bl1 = *(uint32_t*)(sBl + ob + 8);
                #pragma unroll
                for (int mt = 0; mt < 2; mt++) {
                    mma16816(acc[mt][nt], ah[mt], bh0, bh1);
                    mma16816(acc[mt][nt], ah[mt], bl0, bl1);
                    mma16816(acc[mt][nt], al[mt], bh0, bh1);
                }
            }
        }
    }

    // epilogue
    #pragma unroll
    for (int mt = 0; mt < 2; mt++) {
        #pragma unroll
        for (int nt = 0; nt < 8; nt++) {
            int m = bm + wm * 32 + mt * 16 + g;
            int n = bn + wn * 64 + nt * 8 + t4 * 2;
            size_t o0 = ((size_t)z * MD + m) * HWs + n;
            size_t o1 = o0 + 8 * HWs;
            float2 v0 = make_float2(acc[mt][nt][0], acc[mt][nt][1]);
            float2 v1 = make_float2(acc[mt][nt][2], acc[mt][nt][3]);
            if (ADD) {
                float2 r0 = *(const float2*)(R + o0);
                float2 r1 = *(const float2*)(R + o1);
                v0.x += r0.x; v0.y += r0.y;
                v1.x += r1.x; v1.y += r1.y;
            }
            *(float2*)(Y + o0) = v0;
            *(float2*)(Y + o1) = v1;
        }
    }
}

// ---------------------------------------------------------------------------
// Flash-style attention (SIMT); epilogue writes transposed split-bf16
// ---------------------------------------------------------------------------
#define ST 65

__global__ __launch_bounds__(256) void attn_kernel() {
    extern __shared__ float smf[];
    float* Qs = smf;
    float* Ks = smf + 64 * ST;
    float* Vs = smf + 2 * 64 * ST;
    float* Ps = smf + 3 * 64 * ST;

    int rt = blockIdx.x, h = blockIdx.y, b = blockIdx.z;
    int s0 = rt * 64;
    const float* qkvb = g_qkv + (size_t)b * 3 * Cch * HWs;
    const float* Qg = qkvb + (size_t)(h * DH) * HWs;
    const float* Kg = qkvb + (size_t)(Cch + h * DH) * HWs;
    const float* Vg = qkvb + (size_t)(2 * Cch + h * DH) * HWs;

    int tid = threadIdx.x;
    int tx = tid & 15, ty = tid >> 4;

    for (int idx = tid; idx < 4096; idx += 256) {
        int d = idx >> 6, i = idx & 63;
        Qs[d * ST + i] = Qg[(size_t)d * HWs + s0 + i];
    }

    float m[4], l[4], o[4][4];
    #pragma unroll
    for (int i = 0; i < 4; i++) {
        m[i] = -1e30f;
        l[i] = 0.f;
        #pragma unroll
        for (int j = 0; j < 4; j++) o[i][j] = 0.f;
    }
    const float scale = 0.125f;

    for (int kt = 0; kt < 16; kt++) {
        __syncthreads();
        for (int idx = tid; idx < 4096; idx += 256) {
            int d = idx >> 6, j = idx & 63;
            float kvv = Kg[(size_t)d * HWs + kt * 64 + j];
            float vvv = Vg[(size_t)d * HWs + kt * 64 + j];
            Ks[d * ST + j] = kvv;
            Vs[j * ST + d] = vvv;
        }
        __syncthreads();

        float s[4][4];
        #pragma unroll
        for (int i = 0; i < 4; i++)
            #pragma unroll
            for (int j = 0; j < 4; j++) s[i][j] = 0.f;

        #pragma unroll 4
        for (int d = 0; d < 64; d++) {
            float qv[4], kv[4];
            #pragma unroll
            for (int ii = 0; ii < 4; ii++) qv[ii] = Qs[d * ST + 4 * ty + ii];
            #pragma unroll
            for (int jj = 0; jj < 4; jj++) kv[jj] = Ks[d * ST + 4 * tx + jj];
            #pragma unroll
            for (int ii = 0; ii < 4; ii++)
                #pragma unroll
                for (int jj = 0; jj < 4; jj++) s[ii][jj] = fmaf(qv[ii], kv[jj], s[ii][jj]);
        }

        #pragma unroll
        for (int ii = 0; ii < 4; ii++) {
            #pragma unroll
            for (int jj = 0; jj < 4; jj++) s[ii][jj] *= scale;
            float mx = fmaxf(fmaxf(s[ii][0], s[ii][1]), fmaxf(s[ii][2], s[ii][3]));
            #pragma unroll
            for (int off = 8; off; off >>= 1) mx = fmaxf(mx, __shfl_xor_sync(~0u, mx, off));
            float mnew = fmaxf(m[ii], mx);
            float alpha = __expf(m[ii] - mnew);
            float rsum = 0.f;
            #pragma unroll
            for (int jj = 0; jj < 4; jj++) {
                float p = __expf(s[ii][jj] - mnew);
                s[ii][jj] = p;
                rsum += p;
            }
            #pragma unroll
            for (int off = 8; off; off >>= 1) rsum += __shfl_xor_sync(~0u, rsum, off);
            l[ii] = l[ii] * alpha + rsum;
            m[ii] = mnew;
            #pragma unroll
            for (int dd = 0; dd < 4; dd++) o[ii][dd] *= alpha;
        }

        #pragma unroll
        for (int ii = 0; ii < 4; ii++)
            #pragma unroll
            for (int jj = 0; jj < 4; jj++)
                Ps[(4 * tx + jj) * ST + 4 * ty + ii] = s[ii][jj];
        __syncthreads();

        #pragma unroll 4
        for (int j = 0; j < 64; j++) {
            float pv[4], vv[4];
            #pragma unroll
            for (int ii = 0; ii < 4; ii++) pv[ii] = Ps[j * ST + 4 * ty + ii];
            #pragma unroll
            for (int dd = 0; dd < 4; dd++) vv[dd] = Vs[j * ST + 4 * tx + dd];
            #pragma unroll
            for (int ii = 0; ii < 4; ii++)
                #pragma unroll
                for (int dd = 0; dd < 4; dd++) o[ii][dd] = fmaf(pv[ii], vv[dd], o[ii][dd]);
        }
    }

    __syncthreads();
    // stage O as [i][d], normalized
    #pragma unroll
    for (int ii = 0; ii < 4; ii++) {
        float invl = 1.f / l[ii];
        #pragma unroll
        for (int dd = 0; dd < 4; dd++)
            Qs[(4 * ty + ii) * ST + 4 * tx + dd] = o[ii][dd] * invl;
    }
    __syncthreads();
    // write transposed split-bf16: attT[b][s0+i][h*64+d]
    {
        int i = tid >> 2, dbase = (tid & 3) * 16;
        __nv_bfloat16 hv[16], lv[16];
        #pragma unroll
        for (int j = 0; j < 16; j++) bsplit(Qs[i * ST + dbase + j], hv[j], lv[j]);
        size_t ob = ((size_t)b * HWs + s0 + i) * Cch + h * DH + dbase;
        *(uint4*)(g_attT_hi + ob) = *(uint4*)&hv[0];
        *(uint4*)(g_attT_hi + ob + 8) = *(uint4*)&hv[8];
        *(uint4*)(g_attT_lo + ob) = *(uint4*)&lv[0];
        *(uint4*)(g_attT_lo + ob + 8) = *(uint4*)&lv[8];
    }
}

// ---------------------------------------------------------------------------
extern "C" void kernel_launch(void* const* d_in, const int* in_sizes, int n_in,
                              void* d_out, int out_size) {
    const float* x = (const float*)d_in[0];
    const float* gamma = (const float*)d_in[1];
    const float* beta = (const float*)d_in[2];
    const float* w_qkv = (const float*)d_in[3];
    const float* w_out = (const float*)d_in[4];
    float* out = (float*)d_out;

    void *pqkv, *pxh, *pxl, *pah, *pal, *pwqh, *pwql, *pwoh, *pwol;
    cudaGetSymbolAddress(&pqkv, g_qkv);
    cudaGetSymbolAddress(&pxh, g_xnT_hi);
    cudaGetSymbolAddress(&pxl, g_xnT_lo);
    cudaGetSymbolAddress(&pah, g_attT_hi);
    cudaGetSymbolAddress(&pal, g_attT_lo);
    cudaGetSymbolAddress(&pwqh, g_wq_hi);
    cudaGetSymbolAddress(&pwql, g_wq_lo);
    cudaGetSymbolAddress(&pwoh, g_wo_hi);
    cudaGetSymbolAddress(&pwol, g_wo_lo);

    gn_kernel<<<Bsz * 32, 256>>>(x, gamma, beta);
    split_kernel<<<(3 * Cch * KD / 4 + 255) / 256, 256>>>(
        w_qkv, (__nv_bfloat16*)pwqh, (__nv_bfloat16*)pwql, 3 * Cch * KD / 4);
    split_kernel<<<(Cch * KD / 4 + 255) / 256, 256>>>(
        w_out, (__nv_bfloat16*)pwoh, (__nv_bfloat16*)pwol, Cch * KD / 4);

    cudaFuncSetAttribute(gemm_mma<3 * Cch, false>,
                         cudaFuncAttributeMaxDynamicSharedMemorySize, GEMM_SMEM);
    gemm_mma<3 * Cch, false><<<dim3(HWs / 128, 3 * Cch / 128, Bsz), 256, GEMM_SMEM>>>(
        (const __nv_bfloat16*)pwqh, (const __nv_bfloat16*)pwql,
        (const __nv_bfloat16*)pxh, (const __nv_bfloat16*)pxl, (float*)pqkv, nullptr);

    int smem = 4 * 64 * ST * sizeof(float);
    cudaFuncSetAttribute(attn_kernel, cudaFuncAttributeMaxDynamicSharedMemorySize, smem);
    attn_kernel<<<dim3(16, NH, Bsz), 256, smem>>>();

    cudaFuncSetAttribute(gemm_mma<Cch, true>,
                         cudaFuncAttributeMaxDynamicSharedMemorySize, GEMM_SMEM);
    gemm_mma<Cch, true><<<dim3(HWs / 128, Cch / 128, Bsz), 256, GEMM_SMEM>>>(
        (const __nv_bfloat16*)pwoh, (const __nv_bfloat16*)pwol,
        (const __nv_bfloat16*)pah, (const __nv_bfloat16*)pal, out, x);
}

// round 4
// speedup vs baseline: 5.7818x; 4.3820x over previous
#include <cuda_runtime.h>
#include <cuda_bf16.h>
#include <cstdint>

#define Bsz 8
#define Cch 512
#define HWs 1024
#define NH 8
#define DH 64
#define CPG 16
#define EPSV 1e-5f
#define KD 512
#define OD 1536

typedef __nv_bfloat16 bf16;

// Scratch (device globals)
__device__ bf16 g_xnT[(size_t)Bsz * HWs * Cch];   // xn^T [b][s][c]
__device__ bf16 g_qkvT[(size_t)Bsz * HWs * OD];   // qkv^T [b][s][o]
__device__ bf16 g_attT[(size_t)Bsz * HWs * Cch];  // att^T [b][s][c]
__device__ bf16 g_wq[OD * KD];
__device__ bf16 g_wo[Cch * KD];

__device__ __forceinline__ uint32_t smem_u32(const void* p) {
    uint32_t a;
    asm("{ .reg .u64 t; cvta.to.shared.u64 t, %1; cvt.u32.u64 %0, t; }" : "=r"(a) : "l"(p));
    return a;
}
__device__ __forceinline__ void mma16816(float* c, const uint32_t* a, uint32_t b0, uint32_t b1) {
    asm volatile(
        "mma.sync.aligned.m16n8k16.row.col.f32.bf16.bf16.f32 "
        "{%0,%1,%2,%3}, {%4,%5,%6,%7}, {%8,%9}, {%0,%1,%2,%3};"
        : "+f"(c[0]), "+f"(c[1]), "+f"(c[2]), "+f"(c[3])
        : "r"(a[0]), "r"(a[1]), "r"(a[2]), "r"(a[3]), "r"(b0), "r"(b1));
}
__device__ __forceinline__ uint32_t packbf(float a, float b) {
    __nv_bfloat162 t = __floats2bfloat162_rn(a, b);
    return *(uint32_t*)&t;
}

// ---------------------------------------------------------------------------
// GroupNorm -> transposed bf16  xnT[b][s][c]
// ---------------------------------------------------------------------------
__global__ __launch_bounds__(256) void gn_kernel(const float* __restrict__ x,
                                                 const float* __restrict__ gamma,
                                                 const float* __restrict__ beta) {
    int b = blockIdx.x >> 5, g = blockIdx.x & 31;
    size_t base = ((size_t)b * Cch + g * CPG) * HWs;
    const float4* xin = (const float4*)(x + base);
    int tid = threadIdx.x;
    const int N4 = CPG * HWs / 4;
    float s = 0.f, ss = 0.f;
    for (int i = tid; i < N4; i += 256) {
        float4 v = xin[i];
        s += v.x + v.y + v.z + v.w;
        ss += v.x * v.x + v.y * v.y + v.z * v.z + v.w * v.w;
    }
    __shared__ float red[64];
    __shared__ float sga[CPG], sbe[CPG];
    #pragma unroll
    for (int o = 16; o; o >>= 1) {
        s += __shfl_xor_sync(~0u, s, o);
        ss += __shfl_xor_sync(~0u, ss, o);
    }
    if ((tid & 31) == 0) { red[tid >> 5] = s; red[32 + (tid >> 5)] = ss; }
    __syncthreads();
    if (tid < 32) {
        s = (tid < 8) ? red[tid] : 0.f;
        ss = (tid < 8) ? red[32 + tid] : 0.f;
        #pragma unroll
        for (int o = 4; o; o >>= 1) {
            s += __shfl_xor_sync(~0u, s, o);
            ss += __shfl_xor_sync(~0u, ss, o);
        }
        if (tid == 0) { red[0] = s; red[1] = ss; }
    }
    __syncthreads();
    const float invN = 1.f / (CPG * HWs);
    float mean = red[0] * invN;
    float var = red[1] * invN - mean * mean;
    float inv = rsqrtf(var + EPSV);
    if (tid < CPG) {
        int c = g * CPG + tid;
        float ga = gamma[c] * inv;
        sga[tid] = ga;
        sbe[tid] = beta[c] - mean * ga;
    }
    __syncthreads();
    for (int p = tid; p < HWs; p += 256) {
        bf16 hv[CPG];
        #pragma unroll
        for (int j = 0; j < CPG; j++)
            hv[j] = __float2bfloat16(x[base + (size_t)j * HWs + p] * sga[j] + sbe[j]);
        size_t o = ((size_t)b * HWs + p) * Cch + g * CPG;
        *(uint4*)(g_xnT + o) = *(uint4*)&hv[0];
        *(uint4*)(g_xnT + o + 8) = *(uint4*)&hv[8];
    }
}

__global__ __launch_bounds__(256) void split_kernel(const float* __restrict__ src,
                                                    bf16* __restrict__ dst, int n4) {
    int i = blockIdx.x * 256 + threadIdx.x;
    if (i < n4) {
        float4 v = ((const float4*)src)[i];
        bf16 h[4] = {__float2bfloat16(v.x), __float2bfloat16(v.y),
                     __float2bfloat16(v.z), __float2bfloat16(v.w)};
        *(uint2*)(dst + 4 * i) = *(uint2*)h;
    }
}

// ---------------------------------------------------------------------------
// GEMM1: qkvT[z][s][o] = sum_k xnT[z][s][k] * wq[o][k]   (bf16 out)
// Block 128(m=s) x 128(n=o), BK=64, 256 thr, 8 warps 4m x 2n, warp 32x64.
// ---------------------------------------------------------------------------
#define SSTR 72
#define TILE_BYTES (128 * SSTR * 2)
#define GEMM_SMEM (2 * TILE_BYTES)

__global__ __launch_bounds__(256) void gemm_qkv(const bf16* __restrict__ A,
                                                const bf16* __restrict__ B,
                                                bf16* __restrict__ Y) {
    extern __shared__ char sm[];
    bf16* sA = (bf16*)sm;
    bf16* sB = (bf16*)(sm + TILE_BYTES);

    int tid = threadIdx.x, wid = tid >> 5, lane = tid & 31;
    int wm = wid & 3, wn = wid >> 2;
    int g = lane >> 2, t4 = lane & 3;
    int bn = blockIdx.x * 128, bm = blockIdx.y * 128, z = blockIdx.z;

    float acc[2][8][4];
    #pragma unroll
    for (int mt = 0; mt < 2; mt++)
        #pragma unroll
        for (int nt = 0; nt < 8; nt++)
            #pragma unroll
            for (int r = 0; r < 4; r++) acc[mt][nt][r] = 0.f;

    const int frow = tid >> 3, fu = tid & 7;
    const bf16* Ap = A + ((size_t)z * HWs + bm + frow) * KD + fu * 8;
    const bf16* Bp = B + (size_t)(bn + frow) * KD + fu * 8;

    for (int k0 = 0; k0 < KD; k0 += 64) {
        __syncthreads();
        #pragma unroll
        for (int i = 0; i < 4; i++) {
            uint32_t doff = (frow + 32 * i) * SSTR + fu * 8;
            *(uint4*)(sA + doff) = *(const uint4*)(Ap + (size_t)(32 * i) * KD + k0);
            *(uint4*)(sB + doff) = *(const uint4*)(Bp + (size_t)(32 * i) * KD + k0);
        }
        __syncthreads();
        #pragma unroll
        for (int kk = 0; kk < 4; kk++) {
            int kb = kk * 16;
            uint32_t af[2][4];
            #pragma unroll
            for (int mt = 0; mt < 2; mt++) {
                int r0 = wm * 32 + mt * 16 + g;
                uint32_t o00 = r0 * SSTR + kb + t4 * 2;
                af[mt][0] = *(uint32_t*)(sA + o00);
                af[mt][1] = *(uint32_t*)(sA + o00 + 8 * SSTR);
                af[mt][2] = *(uint32_t*)(sA + o00 + 8);
                af[mt][3] = *(uint32_t*)(sA + o00 + 8 * SSTR + 8);
            }
            #pragma unroll
            for (int nt = 0; nt < 8; nt++) {
                uint32_t ob = (wn * 64 + nt * 8 + g) * SSTR + kb + t4 * 2;
                uint32_t b0 = *(uint32_t*)(sB + ob);
                uint32_t b1 = *(uint32_t*)(sB + ob + 8);
                #pragma unroll
                for (int mt = 0; mt < 2; mt++) mma16816(acc[mt][nt], af[mt], b0, b1);
            }
        }
    }
    // epilogue: bf16 store, Y[z][m][n], row stride OD
    #pragma unroll
    for (int mt = 0; mt < 2; mt++) {
        #pragma unroll
        for (int nt = 0; nt < 8; nt++) {
            int m = bm + wm * 32 + mt * 16 + g;
            int n = bn + wn * 64 + nt * 8 + t4 * 2;
            size_t o0 = ((size_t)z * HWs + m) * OD + n;
            *(uint32_t*)(Y + o0) = packbf(acc[mt][nt][0], acc[mt][nt][1]);
            *(uint32_t*)(Y + o0 + 8 * OD) = packbf(acc[mt][nt][2], acc[mt][nt][3]);
        }
    }
}

// ---------------------------------------------------------------------------
// GEMM2: out[z][c][s] = sum_k wo[c][k] * attT[z][s][k] + x[z][c][s]
// A = wo (m=c), B = attT (n=s). fp32 out + residual.
// ---------------------------------------------------------------------------
__global__ __launch_bounds__(256) void gemm_out(const bf16* __restrict__ A,
                                                const bf16* __restrict__ B,
                                                float* __restrict__ Y,
                                                const float* __restrict__ R) {
    extern __shared__ char sm[];
    bf16* sA = (bf16*)sm;
    bf16* sB = (bf16*)(sm + TILE_BYTES);

    int tid = threadIdx.x, wid = tid >> 5, lane = tid & 31;
    int wm = wid & 3, wn = wid >> 2;
    int g = lane >> 2, t4 = lane & 3;
    int bn = blockIdx.x * 128, bm = blockIdx.y * 128, z = blockIdx.z;

    float acc[2][8][4];
    #pragma unroll
    for (int mt = 0; mt < 2; mt++)
        #pragma unroll
        for (int nt = 0; nt < 8; nt++)
            #pragma unroll
            for (int r = 0; r < 4; r++) acc[mt][nt][r] = 0.f;

    const int frow = tid >> 3, fu = tid & 7;
    const bf16* Ap = A + (size_t)(bm + frow) * KD + fu * 8;
    const bf16* Bp = B + ((size_t)z * HWs + bn + frow) * KD + fu * 8;

    for (int k0 = 0; k0 < KD; k0 += 64) {
        __syncthreads();
        #pragma unroll
        for (int i = 0; i < 4; i++) {
            uint32_t doff = (frow + 32 * i) * SSTR + fu * 8;
            *(uint4*)(sA + doff) = *(const uint4*)(Ap + (size_t)(32 * i) * KD + k0);
            *(uint4*)(sB + doff) = *(const uint4*)(Bp + (size_t)(32 * i) * KD + k0);
        }
        __syncthreads();
        #pragma unroll
        for (int kk = 0; kk < 4; kk++) {
            int kb = kk * 16;
            uint32_t af[2][4];
            #pragma unroll
            for (int mt = 0; mt < 2; mt++) {
                int r0 = wm * 32 + mt * 16 + g;
                uint32_t o00 = r0 * SSTR + kb + t4 * 2;
                af[mt][0] = *(uint32_t*)(sA + o00);
                af[mt][1] = *(uint32_t*)(sA + o00 + 8 * SSTR);
                af[mt][2] = *(uint32_t*)(sA + o00 + 8);
                af[mt][3] = *(uint32_t*)(sA + o00 + 8 * SSTR + 8);
            }
            #pragma unroll
            for (int nt = 0; nt < 8; nt++) {
                uint32_t ob = (wn * 64 + nt * 8 + g) * SSTR + kb + t4 * 2;
                uint32_t b0 = *(uint32_t*)(sB + ob);
                uint32_t b1 = *(uint32_t*)(sB + ob + 8);
                #pragma unroll
                for (int mt = 0; mt < 2; mt++) mma16816(acc[mt][nt], af[mt], b0, b1);
            }
        }
    }
    #pragma unroll
    for (int mt = 0; mt < 2; mt++) {
        #pragma unroll
        for (int nt = 0; nt < 8; nt++) {
            int m = bm + wm * 32 + mt * 16 + g;
            int n = bn + wn * 64 + nt * 8 + t4 * 2;
            size_t o0 = ((size_t)z * Cch + m) * HWs + n;
            size_t o1 = o0 + 8 * HWs;
            float2 r0 = *(const float2*)(R + o0);
            float2 r1 = *(const float2*)(R + o1);
            *(float2*)(Y + o0) = make_float2(acc[mt][nt][0] + r0.x, acc[mt][nt][1] + r0.y);
            *(float2*)(Y + o1) = make_float2(acc[mt][nt][2] + r1.x, acc[mt][nt][3] + r1.y);
        }
    }
}

// ---------------------------------------------------------------------------
// MMA flash attention. Br=128, Bc=64, 8 warps (warp = 16 rows).
// qkvT[b][s][o]: q at o=h*64, k at 512+h*64, v at 1024+h*64.
// Writes attT[b][s][h*64+d] bf16.
// ---------------------------------------------------------------------------
#define AST 72
#define ATT_SMEM ((128 + 64 + 64) * AST * 2)

__global__ __launch_bounds__(256) void attn_mma() {
    extern __shared__ char smc[];
    bf16* Qs = (bf16*)smc;                       // [128][AST]
    bf16* Ks = Qs + 128 * AST;                   // [64][AST]
    bf16* Vs = Ks + 64 * AST;                    // [64][AST]

    int rt = blockIdx.x, h = blockIdx.y, b = blockIdx.z;
    int s0 = rt * 128;
    const bf16* qkvT = g_qkvT + (size_t)b * HWs * OD;
    int tid = threadIdx.x, wid = tid >> 5, lane = tid & 31;
    int g = lane >> 2, t4 = lane & 3;
    int r0 = wid * 16;

    // load Q tile
    for (int idx = tid; idx < 1024; idx += 256) {
        int i = idx >> 3, u = idx & 7;
        *(uint4*)(Qs + i * AST + u * 8) =
            *(const uint4*)(qkvT + (size_t)(s0 + i) * OD + h * DH + u * 8);
    }
    __syncthreads();

    uint32_t qf[4][4];
    #pragma unroll
    for (int kk = 0; kk < 4; kk++) {
        const bf16* qp = Qs + (r0 + g) * AST + kk * 16 + t4 * 2;
        qf[kk][0] = *(const uint32_t*)qp;
        qf[kk][1] = *(const uint32_t*)(qp + 8 * AST);
        qf[kk][2] = *(const uint32_t*)(qp + 8);
        qf[kk][3] = *(const uint32_t*)(qp + 8 * AST + 8);
    }

    float mrow0 = -1e30f, mrow1 = -1e30f, lrow0 = 0.f, lrow1 = 0.f;
    float oacc[8][4];
    #pragma unroll
    for (int dt = 0; dt < 8; dt++)
        #pragma unroll
        for (int r = 0; r < 4; r++) oacc[dt][r] = 0.f;

    const bf16* Kg = qkvT + Cch + h * DH;
    const bf16* Vg = qkvT + 2 * Cch + h * DH;
    uint32_t vbase = smem_u32(Vs);
    // ldmatrix lane offset: row = (lane&7) + 8*((lane>>3)&1), col += 8*(lane>>4)
    uint32_t vlane = (((lane & 7) + 8 * ((lane >> 3) & 1)) * AST + 8 * (lane >> 4)) * 2;

    for (int kt = 0; kt < 16; kt++) {
        __syncthreads();
        for (int idx = tid; idx < 512; idx += 256) {
            int j = idx >> 3, u = idx & 7;
            size_t row = (size_t)(kt * 64 + j) * OD + u * 8;
            *(uint4*)(Ks + j * AST + u * 8) = *(const uint4*)(Kg + row);
            *(uint4*)(Vs + j * AST + u * 8) = *(const uint4*)(Vg + row);
        }
        __syncthreads();

        float sf[8][4];
        #pragma unroll
        for (int nt = 0; nt < 8; nt++)
            #pragma unroll
            for (int r = 0; r < 4; r++) sf[nt][r] = 0.f;

        #pragma unroll
        for (int nt = 0; nt < 8; nt++) {
            #pragma unroll
            for (int kk = 0; kk < 4; kk++) {
                const bf16* kp = Ks + (nt * 8 + g) * AST + kk * 16 + t4 * 2;
                uint32_t b0 = *(const uint32_t*)kp;
                uint32_t b1 = *(const uint32_t*)(kp + 8);
                mma16816(sf[nt], qf[kk], b0, b1);
            }
        }

        // online softmax (scale 0.125 applied in exp)
        float mx0 = -1e30f, mx1 = -1e30f;
        #pragma unroll
        for (int nt = 0; nt < 8; nt++) {
            mx0 = fmaxf(mx0, fmaxf(sf[nt][0], sf[nt][1]));
            mx1 = fmaxf(mx1, fmaxf(sf[nt][2], sf[nt][3]));
        }
        mx0 = fmaxf(mx0, __shfl_xor_sync(~0u, mx0, 1));
        mx0 = fmaxf(mx0, __shfl_xor_sync(~0u, mx0, 2));
        mx1 = fmaxf(mx1, __shfl_xor_sync(~0u, mx1, 1));
        mx1 = fmaxf(mx1, __shfl_xor_sync(~0u, mx1, 2));
        float mn0 = fmaxf(mrow0, mx0 * 0.125f);
        float mn1 = fmaxf(mrow1, mx1 * 0.125f);
        float al0 = __expf(mrow0 - mn0);
        float al1 = __expf(mrow1 - mn1);
        float ls0 = 0.f, ls1 = 0.f;
        #pragma unroll
        for (int nt = 0; nt < 8; nt++) {
            float p0 = __expf(fmaf(sf[nt][0], 0.125f, -mn0));
            float p1 = __expf(fmaf(sf[nt][1], 0.125f, -mn0));
            float p2 = __expf(fmaf(sf[nt][2], 0.125f, -mn1));
            float p3 = __expf(fmaf(sf[nt][3], 0.125f, -mn1));
            sf[nt][0] = p0; sf[nt][1] = p1; sf[nt][2] = p2; sf[nt][3] = p3;
            ls0 += p0 + p1;
            ls1 += p2 + p3;
        }
        ls0 += __shfl_xor_sync(~0u, ls0, 1);
        ls0 += __shfl_xor_sync(~0u, ls0, 2);
        ls1 += __shfl_xor_sync(~0u, ls1, 1);
        ls1 += __shfl_xor_sync(~0u, ls1, 2);
        lrow0 = lrow0 * al0 + ls0;
        lrow1 = lrow1 * al1 + ls1;
        mrow0 = mn0;
        mrow1 = mn1;
        #pragma unroll
        for (int dt = 0; dt < 8; dt++) {
            oacc[dt][0] *= al0; oacc[dt][1] *= al0;
            oacc[dt][2] *= al1; oacc[dt][3] *= al1;
        }

        // P frags (bf16) from S accums
        uint32_t pf[4][4];
        #pragma unroll
        for (int kk = 0; kk < 4; kk++) {
            pf[kk][0] = packbf(sf[2 * kk][0], sf[2 * kk][1]);
            pf[kk][1] = packbf(sf[2 * kk][2], sf[2 * kk][3]);
            pf[kk][2] = packbf(sf[2 * kk + 1][0], sf[2 * kk + 1][1]);
            pf[kk][3] = packbf(sf[2 * kk + 1][2], sf[2 * kk + 1][3]);
        }

        // PV: B-frags via ldmatrix.x4.trans from Vs[j][d]
        #pragma unroll
        for (int kk = 0; kk < 4; kk++) {
            #pragma unroll
            for (int np = 0; np < 4; np++) {
                uint32_t addr = vbase + vlane + (kk * 16 * AST + np * 16) * 2;
                uint32_t v0, v1, v2, v3;
                asm volatile(
                    "ldmatrix.sync.aligned.m8n8.x4.trans.shared.b16 {%0,%1,%2,%3}, [%4];"
                    : "=r"(v0), "=r"(v1), "=r"(v2), "=r"(v3) : "r"(addr));
                mma16816(oacc[np * 2], pf[kk], v0, v1);
                mma16816(oacc[np * 2 + 1], pf[kk], v2, v3);
            }
        }
    }

    // epilogue: normalize + bf16 store to attT[b][s][h*64+d]
    float inv0 = 1.f / lrow0, inv1 = 1.f / lrow1;
    bf16* OT = g_attT + ((size_t)b * HWs + s0 + r0 + g) * Cch + h * DH;
    #pragma unroll
    for (int dt = 0; dt < 8; dt++) {
        int n = dt * 8 + t4 * 2;
        *(uint32_t*)(OT + n) = packbf(oacc[dt][0] * inv0, oacc[dt][1] * inv0);
        *(uint32_t*)(OT + 8 * Cch + n) = packbf(oacc[dt][2] * inv1, oacc[dt][3] * inv1);
    }
}

// ---------------------------------------------------------------------------
extern "C" void kernel_launch(void* const* d_in, const int* in_sizes, int n_in,
                              void* d_out, int out_size) {
    const float* x = (const float*)d_in[0];
    const float* gamma = (const float*)d_in[1];
    const float* beta = (const float*)d_in[2];
    const float* w_qkv = (const float*)d_in[3];
    const float* w_out = (const float*)d_in[4];
    float* out = (float*)d_out;

    void *pxn, *pqkv, *patt, *pwq, *pwo;
    cudaGetSymbolAddress(&pxn, g_xnT);
    cudaGetSymbolAddress(&pqkv, g_qkvT);
    cudaGetSymbolAddress(&patt, g_attT);
    cudaGetSymbolAddress(&pwq, g_wq);
    cudaGetSymbolAddress(&pwo, g_wo);

    gn_kernel<<<Bsz * 32, 256>>>(x, gamma, beta);
    split_kernel<<<(OD * KD / 4 + 255) / 256, 256>>>(w_qkv, (bf16*)pwq, OD * KD / 4);
    split_kernel<<<(Cch * KD / 4 + 255) / 256, 256>>>(w_out, (bf16*)pwo, Cch * KD / 4);

    cudaFuncSetAttribute(gemm_qkv, cudaFuncAttributeMaxDynamicSharedMemorySize, GEMM_SMEM);
    gemm_qkv<<<dim3(OD / 128, HWs / 128, Bsz), 256, GEMM_SMEM>>>(
        (const bf16*)pxn, (const bf16*)pwq, (bf16*)pqkv);

    cudaFuncSetAttribute(attn_mma, cudaFuncAttributeMaxDynamicSharedMemorySize, ATT_SMEM);
    attn_mma<<<dim3(HWs / 128, NH, Bsz), 256, ATT_SMEM>>>();

    cudaFuncSetAttribute(gemm_out, cudaFuncAttributeMaxDynamicSharedMemorySize, GEMM_SMEM);
    gemm_out<<<dim3(HWs / 128, Cch / 128, Bsz), 256, GEMM_SMEM>>>(
        (const bf16*)pwo, (const bf16*)patt, out, x);
}

// round 5
// speedup vs baseline: 6.7121x; 1.1609x over previous
#include <cuda_runtime.h>
#include <cuda_bf16.h>
#include <cstdint>

#define Bsz 8
#define Cch 512
#define HWs 1024
#define NH 8
#define DH 64
#define CPG 16
#define EPSV 1e-5f
#define KD 512
#define OD 1536

typedef __nv_bfloat16 bf16;

__device__ bf16 g_xnT[(size_t)Bsz * HWs * Cch];
__device__ bf16 g_qkvT[(size_t)Bsz * HWs * OD];
__device__ bf16 g_attT[(size_t)Bsz * HWs * Cch];
__device__ bf16 g_wq[OD * KD];
__device__ bf16 g_wo[Cch * KD];

__device__ __forceinline__ uint32_t smem_u32(const void* p) {
    uint32_t a;
    asm("{ .reg .u64 t; cvta.to.shared.u64 t, %1; cvt.u32.u64 %0, t; }" : "=r"(a) : "l"(p));
    return a;
}
__device__ __forceinline__ void mma16816(float* c, const uint32_t* a, uint32_t b0, uint32_t b1) {
    asm volatile(
        "mma.sync.aligned.m16n8k16.row.col.f32.bf16.bf16.f32 "
        "{%0,%1,%2,%3}, {%4,%5,%6,%7}, {%8,%9}, {%0,%1,%2,%3};"
        : "+f"(c[0]), "+f"(c[1]), "+f"(c[2]), "+f"(c[3])
        : "r"(a[0]), "r"(a[1]), "r"(a[2]), "r"(a[3]), "r"(b0), "r"(b1));
}
__device__ __forceinline__ uint32_t packbf(float a, float b) {
    __nv_bfloat162 t = __floats2bfloat162_rn(a, b);
    return *(uint32_t*)&t;
}
#define CPA16(dst, src) \
    asm volatile("cp.async.cg.shared.global [%0], [%1], 16;" :: "r"(dst), "l"(src))
#define CPA_COMMIT() asm volatile("cp.async.commit_group;" ::: "memory")
template <int N>
__device__ __forceinline__ void cpa_wait() {
    asm volatile("cp.async.wait_group %0;" :: "n"(N) : "memory");
}
#define LDM4(r0, r1, r2, r3, addr)                                             \
    asm volatile("ldmatrix.sync.aligned.m8n8.x4.shared.b16 {%0,%1,%2,%3}, [%4];" \
                 : "=r"(r0), "=r"(r1), "=r"(r2), "=r"(r3) : "r"(addr))
#define LDM4T(r0, r1, r2, r3, addr)                                            \
    asm volatile("ldmatrix.sync.aligned.m8n8.x4.trans.shared.b16 {%0,%1,%2,%3}, [%4];" \
                 : "=r"(r0), "=r"(r1), "=r"(r2), "=r"(r3) : "r"(addr))

// ---------------------------------------------------------------------------
// GroupNorm -> transposed bf16  xnT[b][s][c]
// ---------------------------------------------------------------------------
__global__ __launch_bounds__(256) void gn_kernel(const float* __restrict__ x,
                                                 const float* __restrict__ gamma,
                                                 const float* __restrict__ beta) {
    int b = blockIdx.x >> 5, g = blockIdx.x & 31;
    size_t base = ((size_t)b * Cch + g * CPG) * HWs;
    const float4* xin = (const float4*)(x + base);
    int tid = threadIdx.x;
    const int N4 = CPG * HWs / 4;
    float s = 0.f, ss = 0.f;
    for (int i = tid; i < N4; i += 256) {
        float4 v = xin[i];
        s += v.x + v.y + v.z + v.w;
        ss += v.x * v.x + v.y * v.y + v.z * v.z + v.w * v.w;
    }
    __shared__ float red[64];
    __shared__ float sga[CPG], sbe[CPG];
    #pragma unroll
    for (int o = 16; o; o >>= 1) {
        s += __shfl_xor_sync(~0u, s, o);
        ss += __shfl_xor_sync(~0u, ss, o);
    }
    if ((tid & 31) == 0) { red[tid >> 5] = s; red[32 + (tid >> 5)] = ss; }
    __syncthreads();
    if (tid < 32) {
        s = (tid < 8) ? red[tid] : 0.f;
        ss = (tid < 8) ? red[32 + tid] : 0.f;
        #pragma unroll
        for (int o = 4; o; o >>= 1) {
            s += __shfl_xor_sync(~0u, s, o);
            ss += __shfl_xor_sync(~0u, ss, o);
        }
        if (tid == 0) { red[0] = s; red[1] = ss; }
    }
    __syncthreads();
    const float invN = 1.f / (CPG * HWs);
    float mean = red[0] * invN;
    float var = red[1] * invN - mean * mean;
    float inv = rsqrtf(var + EPSV);
    if (tid < CPG) {
        int c = g * CPG + tid;
        float ga = gamma[c] * inv;
        sga[tid] = ga;
        sbe[tid] = beta[c] - mean * ga;
    }
    __syncthreads();
    for (int p = tid; p < HWs; p += 256) {
        bf16 hv[CPG];
        #pragma unroll
        for (int j = 0; j < CPG; j++)
            hv[j] = __float2bfloat16(x[base + (size_t)j * HWs + p] * sga[j] + sbe[j]);
        size_t o = ((size_t)b * HWs + p) * Cch + g * CPG;
        *(uint4*)(g_xnT + o) = *(uint4*)&hv[0];
        *(uint4*)(g_xnT + o + 8) = *(uint4*)&hv[8];
    }
}

__global__ __launch_bounds__(256) void split_kernel(const float* __restrict__ src,
                                                    bf16* __restrict__ dst, int n4) {
    int i = blockIdx.x * 256 + threadIdx.x;
    if (i < n4) {
        float4 v = ((const float4*)src)[i];
        bf16 h[4] = {__float2bfloat16(v.x), __float2bfloat16(v.y),
                     __float2bfloat16(v.z), __float2bfloat16(v.w)};
        *(uint2*)(dst + 4 * i) = *(uint2*)h;
    }
}

// ---------------------------------------------------------------------------
// Double-buffered cp.async GEMM, ldmatrix frags.
// Y[(z*ZM + m)*LDY + n] = sum_k A[z][m][k] * B[z][n][k]  (+R)
// Block 128x128, BK=64, 256 thr, 8 warps (4m x 2n), warp tile 32x64.
// ---------------------------------------------------------------------------
#define SSTR 72
#define TILE_BYTES (128 * SSTR * 2)
#define GEMM_SMEM (4 * TILE_BYTES)

template <bool BF16OUT, bool ADD>
__global__ __launch_bounds__(256) void gemm_db(const bf16* __restrict__ A,
                                               const bf16* __restrict__ B,
                                               bf16* __restrict__ Ybf,
                                               float* __restrict__ Yf,
                                               const float* __restrict__ R,
                                               size_t strideAz, size_t strideBz,
                                               int ZM, int LDY) {
    extern __shared__ char sm[];
    uint32_t su = smem_u32(sm);

    int tid = threadIdx.x, wid = tid >> 5, lane = tid & 31;
    int wm = wid & 3, wn = wid >> 2;
    int g = lane >> 2, t4 = lane & 3;
    int bn = blockIdx.x * 128, bm = blockIdx.y * 128, z = blockIdx.z;

    float acc[2][8][4];
    #pragma unroll
    for (int mt = 0; mt < 2; mt++)
        #pragma unroll
        for (int nt = 0; nt < 8; nt++)
            #pragma unroll
            for (int r = 0; r < 4; r++) acc[mt][nt][r] = 0.f;

    const int frow = tid >> 3, fu = tid & 7;
    const bf16* Ap = A + strideAz * z + (size_t)(bm + frow) * KD + fu * 8;
    const bf16* Bp = B + strideBz * z + (size_t)(bn + frow) * KD + fu * 8;

    // stage buffers: [st] A at su + st*2*TILE, B at su + st*2*TILE + TILE
    const uint32_t fillA = (frow * SSTR + fu * 8) * 2;
    const uint32_t fillB = fillA;

    // lane offsets for ldmatrix (elements)
    const uint32_t a_lane = (((lane & 7) + ((lane >> 3) & 1) * 8) * SSTR + (lane >> 4) * 8) * 2;
    const uint32_t b_lane = (((lane & 7) + ((lane >> 4) & 1) * 8) * SSTR + ((lane >> 3) & 1) * 8) * 2;

    // prefetch chunk 0 into stage 0
    #pragma unroll
    for (int i = 0; i < 4; i++) {
        uint32_t off = (uint32_t)(32 * i) * SSTR * 2;
        CPA16(su + fillA + off, Ap + (size_t)(32 * i) * KD);
        CPA16(su + TILE_BYTES + fillB + off, Bp + (size_t)(32 * i) * KD);
    }
    CPA_COMMIT();

    #pragma unroll
    for (int ch = 0; ch < KD / 64; ch++) {
        int st = ch & 1;
        if (ch + 1 < KD / 64) {
            uint32_t sbase = su + ((ch + 1) & 1) * 2 * TILE_BYTES;
            int k0 = (ch + 1) * 64;
            #pragma unroll
            for (int i = 0; i < 4; i++) {
                uint32_t off = (uint32_t)(32 * i) * SSTR * 2;
                CPA16(sbase + fillA + off, Ap + (size_t)(32 * i) * KD + k0);
                CPA16(sbase + TILE_BYTES + fillB + off, Bp + (size_t)(32 * i) * KD + k0);
            }
            CPA_COMMIT();
            cpa_wait<1>();
        } else {
            cpa_wait<0>();
        }
        __syncthreads();

        uint32_t sAu = su + st * 2 * TILE_BYTES;
        uint32_t sBu = sAu + TILE_BYTES;
        #pragma unroll
        for (int kk = 0; kk < 4; kk++) {
            uint32_t kboff = kk * 32;  // 16 elems * 2B
            uint32_t af[2][4];
            #pragma unroll
            for (int mt = 0; mt < 2; mt++) {
                uint32_t addr = sAu + (uint32_t)(wm * 32 + mt * 16) * SSTR * 2 + a_lane + kboff;
                LDM4(af[mt][0], af[mt][1], af[mt][2], af[mt][3], addr);
            }
            #pragma unroll
            for (int np = 0; np < 4; np++) {
                uint32_t addr = sBu + (uint32_t)(wn * 64 + np * 16) * SSTR * 2 + b_lane + kboff;
                uint32_t b0, b1, b2, b3;
                LDM4(b0, b1, b2, b3, addr);
                #pragma unroll
                for (int mt = 0; mt < 2; mt++) {
                    mma16816(acc[mt][2 * np], af[mt], b0, b1);
                    mma16816(acc[mt][2 * np + 1], af[mt], b2, b3);
                }
            }
        }
        __syncthreads();
    }

    #pragma unroll
    for (int mt = 0; mt < 2; mt++) {
        #pragma unroll
        for (int nt = 0; nt < 8; nt++) {
            int m = bm + wm * 32 + mt * 16 + g;
            int n = bn + wn * 64 + nt * 8 + t4 * 2;
            size_t o0 = ((size_t)z * ZM + m) * LDY + n;
            size_t o1 = o0 + (size_t)8 * LDY;
            if (BF16OUT) {
                *(uint32_t*)(Ybf + o0) = packbf(acc[mt][nt][0], acc[mt][nt][1]);
                *(uint32_t*)(Ybf + o1) = packbf(acc[mt][nt][2], acc[mt][nt][3]);
            } else {
                float2 v0 = make_float2(acc[mt][nt][0], acc[mt][nt][1]);
                float2 v1 = make_float2(acc[mt][nt][2], acc[mt][nt][3]);
                if (ADD) {
                    float2 r0 = *(const float2*)(R + o0);
                    float2 r1 = *(const float2*)(R + o1);
                    v0.x += r0.x; v0.y += r0.y;
                    v1.x += r1.x; v1.y += r1.y;
                }
                *(float2*)(Yf + o0) = v0;
                *(float2*)(Yf + o1) = v1;
            }
        }
    }
}

// ---------------------------------------------------------------------------
// MMA flash attention, double-buffered K/V. Br=128, Bc=64, 8 warps.
// ---------------------------------------------------------------------------
#define AST 72
#define QBYTES (128 * AST * 2)
#define KVBYTES (64 * AST * 2)
#define ATT_SMEM (QBYTES + 4 * KVBYTES)

__global__ __launch_bounds__(256) void attn_mma() {
    extern __shared__ char smc[];
    bf16* Qs = (bf16*)smc;
    uint32_t su = smem_u32(smc);
    const uint32_t kvbase = su + QBYTES;  // [st]: K at kvbase+st*2*KVBYTES, V +KVBYTES

    int rt = blockIdx.x, h = blockIdx.y, b = blockIdx.z;
    int s0 = rt * 128;
    const bf16* qkvT = g_qkvT + (size_t)b * HWs * OD;
    int tid = threadIdx.x, wid = tid >> 5, lane = tid & 31;
    int g = lane >> 2, t4 = lane & 3;
    int r0 = wid * 16;

    for (int idx = tid; idx < 1024; idx += 256) {
        int i = idx >> 3, u = idx & 7;
        *(uint4*)(Qs + i * AST + u * 8) =
            *(const uint4*)(qkvT + (size_t)(s0 + i) * OD + h * DH + u * 8);
    }

    const bf16* Kg = qkvT + Cch + h * DH;
    const bf16* Vg = qkvT + 2 * Cch + h * DH;

    // fill offsets: 2 chunks per thread per tensor
    const int j0 = tid >> 3, u0 = tid & 7;
    const int j1 = (tid + 256) >> 3, u1 = tid & 7;
    const uint32_t f0 = (j0 * AST + u0 * 8) * 2, f1 = (j1 * AST + u1 * 8) * 2;

    // prefetch kt=0
    {
        uint32_t kb = kvbase, vb = kvbase + KVBYTES;
        CPA16(kb + f0, Kg + (size_t)j0 * OD + u0 * 8);
        CPA16(kb + f1, Kg + (size_t)j1 * OD + u1 * 8);
        CPA16(vb + f0, Vg + (size_t)j0 * OD + u0 * 8);
        CPA16(vb + f1, Vg + (size_t)j1 * OD + u1 * 8);
    }
    CPA_COMMIT();
    __syncthreads();

    uint32_t qf[4][4];
    #pragma unroll
    for (int kk = 0; kk < 4; kk++) {
        const bf16* qp = Qs + (r0 + g) * AST + kk * 16 + t4 * 2;
        qf[kk][0] = *(const uint32_t*)qp;
        qf[kk][1] = *(const uint32_t*)(qp + 8 * AST);
        qf[kk][2] = *(const uint32_t*)(qp + 8);
        qf[kk][3] = *(const uint32_t*)(qp + 8 * AST + 8);
    }

    float mrow0 = -1e30f, mrow1 = -1e30f, lrow0 = 0.f, lrow1 = 0.f;
    float oacc[8][4];
    #pragma unroll
    for (int dt = 0; dt < 8; dt++)
        #pragma unroll
        for (int r = 0; r < 4; r++) oacc[dt][r] = 0.f;

    const uint32_t k_lane = (((lane & 7) + ((lane >> 4) & 1) * 8) * AST + ((lane >> 3) & 1) * 8) * 2;
    const uint32_t v_lane = ((((lane & 7) + 8 * ((lane >> 3) & 1)) * AST + 8 * (lane >> 4))) * 2;

    for (int kt = 0; kt < 16; kt++) {
        int st = kt & 1;
        if (kt + 1 < 16) {
            uint32_t kb = kvbase + ((kt + 1) & 1) * 2 * KVBYTES;
            uint32_t vb = kb + KVBYTES;
            size_t roff = (size_t)(kt + 1) * 64 * OD;
            CPA16(kb + f0, Kg + roff + (size_t)j0 * OD + u0 * 8);
            CPA16(kb + f1, Kg + roff + (size_t)j1 * OD + u1 * 8);
            CPA16(vb + f0, Vg + roff + (size_t)j0 * OD + u0 * 8);
            CPA16(vb + f1, Vg + roff + (size_t)j1 * OD + u1 * 8);
            CPA_COMMIT();
            cpa_wait<1>();
        } else {
            cpa_wait<0>();
        }
        __syncthreads();

        uint32_t Ku = kvbase + st * 2 * KVBYTES;
        uint32_t Vu = Ku + KVBYTES;

        float sf[8][4];
        #pragma unroll
        for (int nt = 0; nt < 8; nt++)
            #pragma unroll
            for (int r = 0; r < 4; r++) sf[nt][r] = 0.f;

        #pragma unroll
        for (int kk = 0; kk < 4; kk++) {
            uint32_t kboff = kk * 32;
            #pragma unroll
            for (int np = 0; np < 4; np++) {
                uint32_t addr = Ku + (uint32_t)(np * 16) * AST * 2 + k_lane + kboff;
                uint32_t b0, b1, b2, b3;
                LDM4(b0, b1, b2, b3, addr);
                mma16816(sf[2 * np], qf[kk], b0, b1);
                mma16816(sf[2 * np + 1], qf[kk], b2, b3);
            }
        }

        float mx0 = -1e30f, mx1 = -1e30f;
        #pragma unroll
        for (int nt = 0; nt < 8; nt++) {
            mx0 = fmaxf(mx0, fmaxf(sf[nt][0], sf[nt][1]));
            mx1 = fmaxf(mx1, fmaxf(sf[nt][2], sf[nt][3]));
        }
        mx0 = fmaxf(mx0, __shfl_xor_sync(~0u, mx0, 1));
        mx0 = fmaxf(mx0, __shfl_xor_sync(~0u, mx0, 2));
        mx1 = fmaxf(mx1, __shfl_xor_sync(~0u, mx1, 1));
        mx1 = fmaxf(mx1, __shfl_xor_sync(~0u, mx1, 2));
        float mn0 = fmaxf(mrow0, mx0 * 0.125f);
        float mn1 = fmaxf(mrow1, mx1 * 0.125f);
        float al0 = __expf(mrow0 - mn0);
        float al1 = __expf(mrow1 - mn1);
        float ls0 = 0.f, ls1 = 0.f;
        #pragma unroll
        for (int nt = 0; nt < 8; nt++) {
            float p0 = __expf(fmaf(sf[nt][0], 0.125f, -mn0));
            float p1 = __expf(fmaf(sf[nt][1], 0.125f, -mn0));
            float p2 = __expf(fmaf(sf[nt][2], 0.125f, -mn1));
            float p3 = __expf(fmaf(sf[nt][3], 0.125f, -mn1));
            sf[nt][0] = p0; sf[nt][1] = p1; sf[nt][2] = p2; sf[nt][3] = p3;
            ls0 += p0 + p1;
            ls1 += p2 + p3;
        }
        ls0 += __shfl_xor_sync(~0u, ls0, 1);
        ls0 += __shfl_xor_sync(~0u, ls0, 2);
        ls1 += __shfl_xor_sync(~0u, ls1, 1);
        ls1 += __shfl_xor_sync(~0u, ls1, 2);
        lrow0 = lrow0 * al0 + ls0;
        lrow1 = lrow1 * al1 + ls1;
        mrow0 = mn0;
        mrow1 = mn1;
        #pragma unroll
        for (int dt = 0; dt < 8; dt++) {
            oacc[dt][0] *= al0; oacc[dt][1] *= al0;
            oacc[dt][2] *= al1; oacc[dt][3] *= al1;
        }

        uint32_t pf[4][4];
        #pragma unroll
        for (int kk = 0; kk < 4; kk++) {
            pf[kk][0] = packbf(sf[2 * kk][0], sf[2 * kk][1]);
            pf[kk][1] = packbf(sf[2 * kk][2], sf[2 * kk][3]);
            pf[kk][2] = packbf(sf[2 * kk + 1][0], sf[2 * kk + 1][1]);
            pf[kk][3] = packbf(sf[2 * kk + 1][2], sf[2 * kk + 1][3]);
        }

        #pragma unroll
        for (int kk = 0; kk < 4; kk++) {
            #pragma unroll
            for (int np = 0; np < 4; np++) {
                uint32_t addr = Vu + v_lane + (uint32_t)(kk * 16 * AST + np * 16) * 2;
                uint32_t v0, v1, v2, v3;
                LDM4T(v0, v1, v2, v3, addr);
                mma16816(oacc[np * 2], pf[kk], v0, v1);
                mma16816(oacc[np * 2 + 1], pf[kk], v2, v3);
            }
        }
        __syncthreads();
    }

    float inv0 = 1.f / lrow0, inv1 = 1.f / lrow1;
    bf16* OT = g_attT + ((size_t)b * HWs + s0 + r0 + g) * Cch + h * DH;
    #pragma unroll
    for (int dt = 0; dt < 8; dt++) {
        int n = dt * 8 + t4 * 2;
        *(uint32_t*)(OT + n) = packbf(oacc[dt][0] * inv0, oacc[dt][1] * inv0);
        *(uint32_t*)(OT + 8 * Cch + n) = packbf(oacc[dt][2] * inv1, oacc[dt][3] * inv1);
    }
}

// ---------------------------------------------------------------------------
extern "C" void kernel_launch(void* const* d_in, const int* in_sizes, int n_in,
                              void* d_out, int out_size) {
    const float* x = (const float*)d_in[0];
    const float* gamma = (const float*)d_in[1];
    const float* beta = (const float*)d_in[2];
    const float* w_qkv = (const float*)d_in[3];
    const float* w_out = (const float*)d_in[4];
    float* out = (float*)d_out;

    void *pxn, *pqkv, *patt, *pwq, *pwo;
    cudaGetSymbolAddress(&pxn, g_xnT);
    cudaGetSymbolAddress(&pqkv, g_qkvT);
    cudaGetSymbolAddress(&patt, g_attT);
    cudaGetSymbolAddress(&pwq, g_wq);
    cudaGetSymbolAddress(&pwo, g_wo);

    gn_kernel<<<Bsz * 32, 256>>>(x, gamma, beta);
    split_kernel<<<(OD * KD / 4 + 255) / 256, 256>>>(w_qkv, (bf16*)pwq, OD * KD / 4);
    split_kernel<<<(Cch * KD / 4 + 255) / 256, 256>>>(w_out, (bf16*)pwo, Cch * KD / 4);

    cudaFuncSetAttribute(gemm_db<true, false>,
                         cudaFuncAttributeMaxDynamicSharedMemorySize, GEMM_SMEM);
    // qkvT[z][s][o]: A = xnT (m=s), B = wq (n=o)
    gemm_db<true, false><<<dim3(OD / 128, HWs / 128, Bsz), 256, GEMM_SMEM>>>(
        (const bf16*)pxn, (const bf16*)pwq, (bf16*)pqkv, nullptr, nullptr,
        (size_t)HWs * KD, 0, HWs, OD);

    cudaFuncSetAttribute(attn_mma, cudaFuncAttributeMaxDynamicSharedMemorySize, ATT_SMEM);
    attn_mma<<<dim3(HWs / 128, NH, Bsz), 256, ATT_SMEM>>>();

    cudaFuncSetAttribute(gemm_db<false, true>,
                         cudaFuncAttributeMaxDynamicSharedMemorySize, GEMM_SMEM);
    // out[z][c][s]: A = wo (m=c), B = attT (n=s), +residual
    gemm_db<false, true><<<dim3(HWs / 128, Cch / 128, Bsz), 256, GEMM_SMEM>>>(
        (const bf16*)pwo, (const bf16*)patt, nullptr, out, x,
        0, (size_t)HWs * KD, Cch, HWs);
}